// round 13
// baseline (speedup 1.0000x reference)
#include <cuda_runtime.h>
#include <cuda_bf16.h>
#include <cstdint>

typedef unsigned long long u64;
typedef unsigned int u32;

#define NB 16
#define NT 96
#define NN 325
#define ND 64
#define NH 64
#define NROWS (NB*NN)          // 5200
#define BTN (NB*NT*NN)         // 499200
#define HSTRIDE (NN*NH)        // 20800
#define BSTRIDE (NT*NN*NH)     // 1996800

// Fused scratch: [t][row][384] with row = b*NN+n; cols: f,i,o,u,gf,gu (64 each)
__device__ float g_AG[(size_t)BTN * 384];

// ================= helpers =================
__device__ __forceinline__ u32 smem_u32(const void* p){
    u32 a; asm("{ .reg .u64 t; cvta.to.shared.u64 t, %1; cvt.u32.u64 %0, t; }" : "=r"(a) : "l"(p));
    return a;
}
__device__ __forceinline__ u32 bfpack(float lo_elem, float hi_elem){
    u32 r; asm("cvt.rn.bf16x2.f32 %0, %1, %2;" : "=r"(r) : "f"(hi_elem), "f"(lo_elem));
    return r;
}
__device__ __forceinline__ void ldsm_x4(u32& a0,u32& a1,u32& a2,u32& a3, u32 addr){
    asm volatile("ldmatrix.sync.aligned.m8n8.x4.shared.b16 {%0,%1,%2,%3}, [%4];"
      : "=r"(a0),"=r"(a1),"=r"(a2),"=r"(a3) : "r"(addr));
}
__device__ __forceinline__ void ldsm_x2(u32& b0,u32& b1, u32 addr){
    asm volatile("ldmatrix.sync.aligned.m8n8.x2.shared.b16 {%0,%1}, [%2];"
      : "=r"(b0),"=r"(b1) : "r"(addr));
}
__device__ __forceinline__ void mma16816(float* c, const u32* a, const u32* b){
    asm volatile("mma.sync.aligned.m16n8k16.row.col.f32.bf16.bf16.f32 "
      "{%0,%1,%2,%3}, {%4,%5,%6,%7}, {%8,%9}, {%0,%1,%2,%3};"
      : "+f"(c[0]),"+f"(c[1]),"+f"(c[2]),"+f"(c[3])
      : "r"(a[0]),"r"(a[1]),"r"(a[2]),"r"(a[3]), "r"(b[0]),"r"(b[1]));
}

// =====================================================================
// Phase 1 (HMMA, proven R7-R11): per 64-row tile fused [xUx+bx | oUg+bg]
// (N=384), split-3 bf16, register prefetch pipelining.
// =====================================================================
#define P1_THREADS 256
#define P1_ROWS 64
#define P1_TILES (BTN/P1_ROWS)   // 7800
#define P1_GRID 148

#define PITCH 400
#define S_BIAS 0
#define S_B    1536
#define S_AX   155136
#define S_AO   180736
#define P1_SMEM 206336

__global__ void __launch_bounds__(P1_THREADS, 1)
glstm_pre_mma(const float* __restrict__ x, const float* __restrict__ osrc,
              const float* __restrict__ Ux, const float* __restrict__ bx,
              const float* __restrict__ Ug, const float* __restrict__ bg)
{
    extern __shared__ unsigned char smem[];
    float* bias_s = (float*)(smem + S_BIAS);
    const int tid = threadIdx.x;
    const int w   = tid >> 5;
    const int lane = tid & 31;
    const int gid = lane >> 2, tid4 = lane & 3;

    bias_s[tid] = bx[tid];
    if (tid < 128) bias_s[256 + tid] = bg[tid];

    for (int i = tid; i < 64*256; i += P1_THREADS){
        int n = i & 255, k = i >> 8;
        float v = Ux[k*256 + n];
        __nv_bfloat16 hb = __float2bfloat16(v);
        float lo = v - __bfloat162float(hb);
        __nv_bfloat16* row = (__nv_bfloat16*)(smem + S_B + n*PITCH);
        row[k] = hb; row[128 + k] = hb;
        row[64 + k] = __float2bfloat16(lo);
    }
    for (int i = tid; i < 64*128; i += P1_THREADS){
        int n = i & 127, k = i >> 7;
        float v = Ug[k*128 + n];
        __nv_bfloat16 hb = __float2bfloat16(v);
        float lo = v - __bfloat162float(hb);
        __nv_bfloat16* row = (__nv_bfloat16*)(smem + S_B + (256 + n)*PITCH);
        row[k] = hb; row[128 + k] = hb;
        row[64 + k] = __float2bfloat16(lo);
    }

    const u32 sb = smem_u32(smem);
    u32 rowAx[4], rowAo[4];
    #pragma unroll
    for (int mi = 0; mi < 4; mi++){
        u32 off = (u32)(16*mi + (lane & 15))*PITCH + ((lane >> 4) << 4);
        rowAx[mi] = sb + S_AX + off;
        rowAo[mi] = sb + S_AO + off;
    }
    u32 rowB[6];
    #pragma unroll
    for (int ni = 0; ni < 6; ni++)
        rowB[ni] = sb + S_B + (u32)(48*w + 8*ni + (lane & 7))*PITCH + (((lane >> 3) & 1) << 4);

    const bool needx = (w <= 5), needo = (w >= 5);

    const int cr = tid >> 2, ck0 = (tid & 3) << 4;
    u32* ax32 = (u32*)(smem + S_AX + cr*PITCH);
    u32* ao32 = (u32*)(smem + S_AO + cr*PITCH);

    int tile = blockIdx.x;
    float4 xv[4], ov[4];
    {
        const float4* xp = (const float4*)(x    + (size_t)((long long)tile*P1_ROWS + cr)*64 + ck0);
        const float4* op = (const float4*)(osrc + (size_t)((long long)tile*P1_ROWS + cr)*64 + ck0);
        #pragma unroll
        for (int j = 0; j < 4; j++){ xv[j] = xp[j]; ov[j] = op[j]; }
    }

    while (tile < P1_TILES){
        const long long m0 = (long long)tile * P1_ROWS;

        #pragma unroll
        for (int j = 0; j < 4; j++){
            #pragma unroll
            for (int h = 0; h < 2; h++){
                float a = h ? xv[j].z : xv[j].x;
                float b = h ? xv[j].w : xv[j].y;
                int k = ck0 + 4*j + 2*h;
                u32 hp = bfpack(a, b);
                float ra = a - __uint_as_float(hp << 16);
                float rb = b - __uint_as_float(hp & 0xFFFF0000u);
                u32 lp = bfpack(ra, rb);
                ax32[k>>1] = hp; ax32[32 + (k>>1)] = hp; ax32[64 + (k>>1)] = lp;

                a = h ? ov[j].z : ov[j].x;
                b = h ? ov[j].w : ov[j].y;
                hp = bfpack(a, b);
                ra = a - __uint_as_float(hp << 16);
                rb = b - __uint_as_float(hp & 0xFFFF0000u);
                lp = bfpack(ra, rb);
                ao32[k>>1] = hp; ao32[32 + (k>>1)] = hp; ao32[64 + (k>>1)] = lp;
            }
        }
        __syncthreads();

        const int nxt = tile + gridDim.x;
        if (nxt < P1_TILES){
            const float4* xp = (const float4*)(x    + (size_t)((long long)nxt*P1_ROWS + cr)*64 + ck0);
            const float4* op = (const float4*)(osrc + (size_t)((long long)nxt*P1_ROWS + cr)*64 + ck0);
            #pragma unroll
            for (int j = 0; j < 4; j++){ xv[j] = xp[j]; ov[j] = op[j]; }
        }

        float acc[4][6][4];
        #pragma unroll
        for (int mi = 0; mi < 4; mi++)
            #pragma unroll
            for (int ni = 0; ni < 6; ni++)
                #pragma unroll
                for (int e = 0; e < 4; e++) acc[mi][ni][e] = 0.0f;

        #pragma unroll
        for (int kf = 0; kf < 12; kf++){
            u32 Axf[4][4], Aof[4][4];
            if (needx){
                #pragma unroll
                for (int mi = 0; mi < 4; mi++)
                    ldsm_x4(Axf[mi][0],Axf[mi][1],Axf[mi][2],Axf[mi][3], rowAx[mi] + kf*32);
            }
            if (needo){
                #pragma unroll
                for (int mi = 0; mi < 4; mi++)
                    ldsm_x4(Aof[mi][0],Aof[mi][1],Aof[mi][2],Aof[mi][3], rowAo[mi] + kf*32);
            }
            u32 Bf[6][2];
            #pragma unroll
            for (int ni = 0; ni < 6; ni++)
                ldsm_x2(Bf[ni][0], Bf[ni][1], rowB[ni] + kf*32);

            #pragma unroll
            for (int ni = 0; ni < 6; ni++){
                const bool isx = (48*w + 8*ni) < 256;
                #pragma unroll
                for (int mi = 0; mi < 4; mi++)
                    mma16816(acc[mi][ni], isx ? Axf[mi] : Aof[mi], Bf[ni]);
            }
        }
        __syncthreads();

        #pragma unroll
        for (int mi = 0; mi < 4; mi++){
            #pragma unroll
            for (int half = 0; half < 2; half++){
                int r = 16*mi + gid + 8*half;
                long long m = m0 + r;
                u32 mu = (u32)m;
                u32 qq = mu / NN;
                u32 n  = mu - qq*NN;
                u32 t  = qq % NT, b = qq / NT;
                size_t ro = (size_t)t*NROWS + (size_t)b*NN + n;
                float* pAG = g_AG + ro*384;
                #pragma unroll
                for (int ni = 0; ni < 6; ni++){
                    int col = 48*w + 8*ni + 2*tid4;
                    float2 bv = *(const float2*)&bias_s[col];
                    float2 cv;
                    cv.x = acc[mi][ni][half*2 + 0] + bv.x;
                    cv.y = acc[mi][ni][half*2 + 1] + bv.y;
                    *(float2*)(pAG + col) = cv;
                }
            }
        }
        tile = nxt;
    }
}

// =====================================================================
// Phase 2: HMMA recurrence, gate-aligned fragments, 2 CTAs/SM.
// 260 blocks x 20 rows (exact, single wave at occupancy 2).
// Per block: 2 m16 tiles (rows pad to 32), single h buffer, 2 barriers
// per step. acc init = direct LDG of apre (latency hidden by co-CTA).
// =====================================================================
#define P2_THREADS 256
#define P2_R 20
#define P2_BLOCKS 260
#define HPITCH 272                   // bytes per h/B row (hi 128 | lo 128 + pad)
#define SB_B   0                     // 384*272 = 104448
#define SB_H   104448                // 32*272 = 8704
#define P2_SMEM (104448 + 8704)      // 113152

// one element-pair LSTM update from 12 gate scalars (proven math)
__device__ __forceinline__ void lstm_pair(
    float gf0, float gi0, float go0, float gu0, float gG0, float gV0,
    float gf1, float gi1, float go1, float gu1, float gG1, float gV1,
    float& c0, float& c1, float& hn0, float& hn1)
{
    {
        float ef = __expf(-gf0);
        float eg = __expf(-gG0);
        float fgf = __fdividef(1.0f, 1.0f + ef + eg + ef*eg);
        float ei = __expf(-gi0);
        float eu = __expf(-gu0);
        float ev = __expf(-gV0);
        float iuu = __fdividef(1.0f, (1.0f+ei)*(1.0f+eu)*(1.0f+ev));
        float c = fgf*c0 + iuu;
        c0 = c;
        float ot = __fdividef(1.0f, 1.0f + __expf(-go0));
        float th = 1.0f - __fdividef(2.0f, 1.0f + __expf(2.0f*c));
        hn0 = ot * th;
    }
    {
        float ef = __expf(-gf1);
        float eg = __expf(-gG1);
        float fgf = __fdividef(1.0f, 1.0f + ef + eg + ef*eg);
        float ei = __expf(-gi1);
        float eu = __expf(-gu1);
        float ev = __expf(-gV1);
        float iuu = __fdividef(1.0f, (1.0f+ei)*(1.0f+eu)*(1.0f+ev));
        float c = fgf*c1 + iuu;
        c1 = c;
        float ot = __fdividef(1.0f, 1.0f + __expf(-go1));
        float th = 1.0f - __fdividef(2.0f, 1.0f + __expf(2.0f*c));
        hn1 = ot * th;
    }
}

__global__ void __launch_bounds__(P2_THREADS, 2)
glstm_rec_mma(const float* __restrict__ Vx, const float* __restrict__ Vg,
              float* __restrict__ hidden, float* __restrict__ htp, float* __restrict__ ctp)
{
    extern __shared__ unsigned char smem[];
    const u32 sb = smem_u32(smem);

    const int tid  = threadIdx.x;
    const int lane = tid & 31;
    const int w    = tid >> 5;      // 0..7
    const int gid  = lane >> 2, tid4 = lane & 3;
    const int blk  = blockIdx.x;
    const int hcol = 8*w + 2*tid4;  // h column pair owned by this thread
    const int hpi  = 4*w + tid4;
    const bool rg2v = (gid < 4);    // rows 16..19 valid

    // ---- build fused B = [Vx | Vg] rows n=0..383 as [hi(64)|lo(64)] bf16 ----
    for (int i = tid; i < 64*384; i += P2_THREADS){
        int k = i / 384, n = i - k*384;
        float v = (n < 256) ? Vx[k*256 + n] : Vg[k*128 + (n - 256)];
        __nv_bfloat16 hb = __float2bfloat16(v);
        __nv_bfloat16* row = (__nv_bfloat16*)(smem + SB_B + n*HPITCH);
        row[k]      = hb;
        row[64 + k] = __float2bfloat16(v - __bfloat162float(hb));
    }
    // ---- zero h buffer (32 rows incl. pad; pad rows stay zero forever) ----
    for (int i = tid; i < 8704/4; i += P2_THREADS)
        ((u32*)(smem + SB_H))[i] = 0;

    // B ldmatrix addresses: gate g -> rows 64g + 8w .. +7
    u32 rowB[6];
    #pragma unroll
    for (int g = 0; g < 6; g++)
        rowB[g] = sb + SB_B + (u32)(64*g + 8*w + (lane & 7))*HPITCH
                + (((lane >> 3) & 1) << 4);

    // A ldmatrix bases: 2 m16 tiles
    u32 rowA[2];
    #pragma unroll
    for (int mi = 0; mi < 2; mi++)
        rowA[mi] = sb + SB_H + (u32)(16*mi + (lane & 15))*HPITCH + ((lane >> 4) << 4);

    // row groups: rg0 -> r=gid, rg1 -> r=8+gid, rg2 -> r=16+gid (gid<4)
    int rr[3], gb[3], fb[3];
    float cst0[3], cst1[3];
    #pragma unroll
    for (int rg = 0; rg < 3; rg++){
        int r = 8*rg + gid;
        rr[rg] = r;
        int rho = blk*P2_R + ((rg == 2 && !rg2v) ? 0 : r);   // clamp for safety
        int b = rho / NN, n = rho - b*NN;
        gb[rg] = b*BSTRIDE + n*NH + hcol;
        fb[rg] = rho*NH + hcol;
        cst0[rg] = 0.0f; cst1[rg] = 0.0f;
    }
    __syncthreads();

    for (int t = 0; t < NT; t++){
        // ---- acc init = direct LDG of apre (hidden by co-resident CTA) ----
        float acc[2][6][4];
        {
            const float* base = g_AG + ((size_t)t*NROWS + (size_t)blk*P2_R)*384 + hcol;
            const float* p0 = base + (size_t)(gid)*384;
            const float* p1 = base + (size_t)(8 + gid)*384;
            const float* p2 = base + (size_t)(16 + gid)*384;
            #pragma unroll
            for (int g = 0; g < 6; g++){
                float2 a0 = *(const float2*)(p0 + 64*g);
                float2 a1 = *(const float2*)(p1 + 64*g);
                acc[0][g][0] = a0.x; acc[0][g][1] = a0.y;
                acc[0][g][2] = a1.x; acc[0][g][3] = a1.y;
                if (rg2v){
                    float2 a2 = *(const float2*)(p2 + 64*g);
                    acc[1][g][0] = a2.x; acc[1][g][1] = a2.y;
                } else {
                    acc[1][g][0] = 0.0f; acc[1][g][1] = 0.0f;
                }
                acc[1][g][2] = 0.0f; acc[1][g][3] = 0.0f;
            }
        }

        // ---- MMA: fused split-3 per kf, 2 tiles ----
        #pragma unroll
        for (int kf = 0; kf < 4; kf++){
            u32 Ah[2][4], Al[2][4];
            #pragma unroll
            for (int mi = 0; mi < 2; mi++){
                ldsm_x4(Ah[mi][0],Ah[mi][1],Ah[mi][2],Ah[mi][3], rowA[mi] + kf*32);
                ldsm_x4(Al[mi][0],Al[mi][1],Al[mi][2],Al[mi][3], rowA[mi] + 128 + kf*32);
            }
            u32 Bh[6][2], Bl[6][2];
            #pragma unroll
            for (int g = 0; g < 6; g++){
                ldsm_x2(Bh[g][0], Bh[g][1], rowB[g] + kf*32);
                ldsm_x2(Bl[g][0], Bl[g][1], rowB[g] + 128 + kf*32);
            }
            #pragma unroll
            for (int g = 0; g < 6; g++)
                #pragma unroll
                for (int mi = 0; mi < 2; mi++){
                    mma16816(acc[mi][g], Ah[mi], Bh[g]);
                    mma16816(acc[mi][g], Ah[mi], Bl[g]);
                    mma16816(acc[mi][g], Al[mi], Bh[g]);
                }
        }
        __syncthreads();   // all ldsm reads of h(t-1) complete

        // ---- EW fully in registers: rg0,rg1,rg2(guarded) ----
        #pragma unroll
        for (int rg = 0; rg < 3; rg++){
            if (rg == 2 && !rg2v) continue;
            int mi = rg >> 1, hm = rg & 1;
            float hn0, hn1;
            lstm_pair(acc[mi][0][2*hm], acc[mi][1][2*hm], acc[mi][2][2*hm],
                      acc[mi][3][2*hm], acc[mi][4][2*hm], acc[mi][5][2*hm],
                      acc[mi][0][2*hm+1], acc[mi][1][2*hm+1], acc[mi][2][2*hm+1],
                      acc[mi][3][2*hm+1], acc[mi][4][2*hm+1], acc[mi][5][2*hm+1],
                      cst0[rg], cst1[rg], hn0, hn1);

            u32 hhi = bfpack(hn0, hn1);
            float r0 = hn0 - __uint_as_float(hhi << 16);
            float r1 = hn1 - __uint_as_float(hhi & 0xFFFF0000u);
            u32 hlo = bfpack(r0, r1);
            *(u32*)(smem + SB_H + rr[rg]*HPITCH + 4*hpi)       = hhi;
            *(u32*)(smem + SB_H + rr[rg]*HPITCH + 128 + 4*hpi) = hlo;

            float2 hv = make_float2(hn0, hn1);
            *(float2*)&hidden[gb[rg] + t*HSTRIDE] = hv;
            if (t == NT-1){
                *(float2*)&htp[fb[rg]] = hv;
                *(float2*)&ctp[fb[rg]] = make_float2(cst0[rg], cst1[rg]);
            }
        }
        __syncthreads();   // h(t) published before step t+1 ldsm
    }
}

extern "C" void kernel_launch(void* const* d_in, const int* in_sizes, int n_in,
                              void* d_out, int out_size)
{
    const float* x   = (const float*)d_in[0];
    const float* o_s = (const float*)d_in[1];
    const float* Ux  = (const float*)d_in[2];
    const float* Vx  = (const float*)d_in[3];
    const float* bx  = (const float*)d_in[4];
    const float* Ug  = (const float*)d_in[5];
    const float* Vg  = (const float*)d_in[6];
    const float* bg  = (const float*)d_in[7];

    float* out    = (float*)d_out;
    float* hidden = out;                               // [B,T,N,H]
    float* htp    = out + (size_t)BTN * NH;            // [B,N,H]
    float* ctp    = htp + (size_t)NROWS * NH;          // [B,N,H]

    cudaFuncSetAttribute(glstm_pre_mma, cudaFuncAttributeMaxDynamicSharedMemorySize, P1_SMEM);
    cudaFuncSetAttribute(glstm_rec_mma, cudaFuncAttributeMaxDynamicSharedMemorySize, P2_SMEM);

    glstm_pre_mma<<<P1_GRID, P1_THREADS, P1_SMEM>>>(x, o_s, Ux, bx, Ug, bg);
    glstm_rec_mma<<<P2_BLOCKS, P2_THREADS, P2_SMEM>>>(Vx, Vg, hidden, htp, ctp);
}

// round 14
// speedup vs baseline: 1.1903x; 1.1903x over previous
#include <cuda_runtime.h>
#include <cuda_bf16.h>
#include <cstdint>

typedef unsigned long long u64;
typedef unsigned int u32;

#define NB 16
#define NT 96
#define NN 325
#define ND 64
#define NH 64
#define NROWS (NB*NN)          // 5200
#define BTN (NB*NT*NN)         // 499200
#define HSTRIDE (NN*NH)        // 20800
#define BSTRIDE (NT*NN*NH)     // 1996800

// Fused scratch: [t][row][384] with row = b*NN+n; cols: f,i,o,u,gf,gu (64 each)
__device__ float g_AG[(size_t)BTN * 384];

// ================= helpers =================
__device__ __forceinline__ u32 smem_u32(const void* p){
    u32 a; asm("{ .reg .u64 t; cvta.to.shared.u64 t, %1; cvt.u32.u64 %0, t; }" : "=r"(a) : "l"(p));
    return a;
}
__device__ __forceinline__ u32 bfpack(float lo_elem, float hi_elem){
    u32 r; asm("cvt.rn.bf16x2.f32 %0, %1, %2;" : "=r"(r) : "f"(hi_elem), "f"(lo_elem));
    return r;
}
__device__ __forceinline__ void ldsm_x4(u32& a0,u32& a1,u32& a2,u32& a3, u32 addr){
    asm volatile("ldmatrix.sync.aligned.m8n8.x4.shared.b16 {%0,%1,%2,%3}, [%4];"
      : "=r"(a0),"=r"(a1),"=r"(a2),"=r"(a3) : "r"(addr));
}
__device__ __forceinline__ void ldsm_x2(u32& b0,u32& b1, u32 addr){
    asm volatile("ldmatrix.sync.aligned.m8n8.x2.shared.b16 {%0,%1}, [%2];"
      : "=r"(b0),"=r"(b1) : "r"(addr));
}
__device__ __forceinline__ void mma16816(float* c, const u32* a, const u32* b){
    asm volatile("mma.sync.aligned.m16n8k16.row.col.f32.bf16.bf16.f32 "
      "{%0,%1,%2,%3}, {%4,%5,%6,%7}, {%8,%9}, {%0,%1,%2,%3};"
      : "+f"(c[0]),"+f"(c[1]),"+f"(c[2]),"+f"(c[3])
      : "r"(a[0]),"r"(a[1]),"r"(a[2]),"r"(a[3]), "r"(b[0]),"r"(b[1]));
}

// =====================================================================
// Phase 1 (HMMA): per 64-row tile fused [xUx+bx | oUg+bg] (N=384),
// split-3 bf16, register prefetch. NOW 512 threads (16 warps x 24 cols)
// for latency hiding at occ 25%.
// =====================================================================
#define P1_THREADS 512
#define P1_ROWS 64
#define P1_TILES (BTN/P1_ROWS)   // 7800
#define P1_GRID 148

#define PITCH 400
#define S_BIAS 0
#define S_B    1536
#define S_AX   155136
#define S_AO   180736
#define P1_SMEM 206336

__global__ void __launch_bounds__(P1_THREADS, 1)
glstm_pre_mma(const float* __restrict__ x, const float* __restrict__ osrc,
              const float* __restrict__ Ux, const float* __restrict__ bx,
              const float* __restrict__ Ug, const float* __restrict__ bg)
{
    extern __shared__ unsigned char smem[];
    float* bias_s = (float*)(smem + S_BIAS);
    const int tid = threadIdx.x;
    const int w   = tid >> 5;        // 0..15
    const int lane = tid & 31;
    const int gid = lane >> 2, tid4 = lane & 3;

    if (tid < 256) bias_s[tid] = bx[tid];
    if (tid < 128) bias_s[256 + tid] = bg[tid];

    for (int i = tid; i < 64*256; i += P1_THREADS){
        int n = i & 255, k = i >> 8;
        float v = Ux[k*256 + n];
        __nv_bfloat16 hb = __float2bfloat16(v);
        float lo = v - __bfloat162float(hb);
        __nv_bfloat16* row = (__nv_bfloat16*)(smem + S_B + n*PITCH);
        row[k] = hb; row[128 + k] = hb;
        row[64 + k] = __float2bfloat16(lo);
    }
    for (int i = tid; i < 64*128; i += P1_THREADS){
        int n = i & 127, k = i >> 7;
        float v = Ug[k*128 + n];
        __nv_bfloat16 hb = __float2bfloat16(v);
        float lo = v - __bfloat162float(hb);
        __nv_bfloat16* row = (__nv_bfloat16*)(smem + S_B + (256 + n)*PITCH);
        row[k] = hb; row[128 + k] = hb;
        row[64 + k] = __float2bfloat16(lo);
    }

    const u32 sb = smem_u32(smem);
    u32 rowAx[4], rowAo[4];
    #pragma unroll
    for (int mi = 0; mi < 4; mi++){
        u32 off = (u32)(16*mi + (lane & 15))*PITCH + ((lane >> 4) << 4);
        rowAx[mi] = sb + S_AX + off;
        rowAo[mi] = sb + S_AO + off;
    }
    u32 rowB[3];
    #pragma unroll
    for (int ni = 0; ni < 3; ni++)
        rowB[ni] = sb + S_B + (u32)(24*w + 8*ni + (lane & 7))*PITCH + (((lane >> 3) & 1) << 4);

    const bool needx = (w <= 10), needo = (w >= 10);

    // conversion mapping: 8 threads per row, 8 k-elems per thread
    const int cr = tid >> 3, ck0 = (tid & 7) << 3;
    u32* ax32 = (u32*)(smem + S_AX + cr*PITCH);
    u32* ao32 = (u32*)(smem + S_AO + cr*PITCH);

    int tile = blockIdx.x;
    float4 xv[2], ov[2];
    {
        const float4* xp = (const float4*)(x    + (size_t)((long long)tile*P1_ROWS + cr)*64 + ck0);
        const float4* op = (const float4*)(osrc + (size_t)((long long)tile*P1_ROWS + cr)*64 + ck0);
        #pragma unroll
        for (int j = 0; j < 2; j++){ xv[j] = xp[j]; ov[j] = op[j]; }
    }

    while (tile < P1_TILES){
        const long long m0 = (long long)tile * P1_ROWS;

        #pragma unroll
        for (int j = 0; j < 2; j++){
            #pragma unroll
            for (int h = 0; h < 2; h++){
                float a = h ? xv[j].z : xv[j].x;
                float b = h ? xv[j].w : xv[j].y;
                int k = ck0 + 4*j + 2*h;
                u32 hp = bfpack(a, b);
                float ra = a - __uint_as_float(hp << 16);
                float rb = b - __uint_as_float(hp & 0xFFFF0000u);
                u32 lp = bfpack(ra, rb);
                ax32[k>>1] = hp; ax32[32 + (k>>1)] = hp; ax32[64 + (k>>1)] = lp;

                a = h ? ov[j].z : ov[j].x;
                b = h ? ov[j].w : ov[j].y;
                hp = bfpack(a, b);
                ra = a - __uint_as_float(hp << 16);
                rb = b - __uint_as_float(hp & 0xFFFF0000u);
                lp = bfpack(ra, rb);
                ao32[k>>1] = hp; ao32[32 + (k>>1)] = hp; ao32[64 + (k>>1)] = lp;
            }
        }
        __syncthreads();

        const int nxt = tile + gridDim.x;
        if (nxt < P1_TILES){
            const float4* xp = (const float4*)(x    + (size_t)((long long)nxt*P1_ROWS + cr)*64 + ck0);
            const float4* op = (const float4*)(osrc + (size_t)((long long)nxt*P1_ROWS + cr)*64 + ck0);
            #pragma unroll
            for (int j = 0; j < 2; j++){ xv[j] = xp[j]; ov[j] = op[j]; }
        }

        float acc[4][3][4];
        #pragma unroll
        for (int mi = 0; mi < 4; mi++)
            #pragma unroll
            for (int ni = 0; ni < 3; ni++)
                #pragma unroll
                for (int e = 0; e < 4; e++) acc[mi][ni][e] = 0.0f;

        #pragma unroll
        for (int kf = 0; kf < 12; kf++){
            u32 Axf[4][4], Aof[4][4];
            if (needx){
                #pragma unroll
                for (int mi = 0; mi < 4; mi++)
                    ldsm_x4(Axf[mi][0],Axf[mi][1],Axf[mi][2],Axf[mi][3], rowAx[mi] + kf*32);
            }
            if (needo){
                #pragma unroll
                for (int mi = 0; mi < 4; mi++)
                    ldsm_x4(Aof[mi][0],Aof[mi][1],Aof[mi][2],Aof[mi][3], rowAo[mi] + kf*32);
            }
            u32 Bf[3][2];
            #pragma unroll
            for (int ni = 0; ni < 3; ni++)
                ldsm_x2(Bf[ni][0], Bf[ni][1], rowB[ni] + kf*32);

            #pragma unroll
            for (int ni = 0; ni < 3; ni++){
                const bool isx = (24*w + 8*ni) < 256;
                #pragma unroll
                for (int mi = 0; mi < 4; mi++)
                    mma16816(acc[mi][ni], isx ? Axf[mi] : Aof[mi], Bf[ni]);
            }
        }
        __syncthreads();

        #pragma unroll
        for (int mi = 0; mi < 4; mi++){
            #pragma unroll
            for (int half = 0; half < 2; half++){
                int r = 16*mi + gid + 8*half;
                long long m = m0 + r;
                u32 mu = (u32)m;
                u32 qq = mu / NN;
                u32 n  = mu - qq*NN;
                u32 t  = qq % NT, b = qq / NT;
                size_t ro = (size_t)t*NROWS + (size_t)b*NN + n;
                float* pAG = g_AG + ro*384;
                #pragma unroll
                for (int ni = 0; ni < 3; ni++){
                    int col = 24*w + 8*ni + 2*tid4;
                    float2 bv = *(const float2*)&bias_s[col];
                    float2 cv;
                    cv.x = acc[mi][ni][half*2 + 0] + bv.x;
                    cv.y = acc[mi][ni][half*2 + 1] + bv.y;
                    *(float2*)(pAG + col) = cv;
                }
            }
        }
        tile = nxt;
    }
}

// =====================================================================
// Phase 2 (R11 structure, re-gridded): 148 blocks x 36 rows (5328>=5200,
// guarded). Gate-aligned fragments, EW in-register, apre reg prefetch,
// ping-pong h buffers, ONE __syncthreads per step. 256 threads, 8 warps.
// =====================================================================
#define P2_THREADS 256
#define P2_R 36
#define P2_BLOCKS 148
#define HPITCH 272                   // bytes per h/B row (hi 128 | lo 128 + pad)
#define SB_B   0                     // 384*272 = 104448
#define SB_H0  104448                // 48*272 = 13056
#define SB_H1  (104448 + 13056)
#define P2_SMEM (104448 + 2*13056)   // 130560

__global__ void __launch_bounds__(P2_THREADS, 1)
glstm_rec_mma(const float* __restrict__ Vx, const float* __restrict__ Vg,
              float* __restrict__ hidden, float* __restrict__ htp, float* __restrict__ ctp)
{
    extern __shared__ unsigned char smem[];
    const u32 sb = smem_u32(smem);

    const int tid  = threadIdx.x;
    const int lane = tid & 31;
    const int w    = tid >> 5;      // 0..7
    const int gid  = lane >> 2, tid4 = lane & 3;
    const int blk  = blockIdx.x;
    const int hcol = 8*w + 2*tid4;  // h column pair owned by this thread
    const int hpi  = 4*w + tid4;

    // ---- build fused B = [Vx | Vg] rows n=0..383 as [hi(64)|lo(64)] bf16 ----
    for (int i = tid; i < 64*384; i += P2_THREADS){
        int k = i / 384, n = i - k*384;
        float v = (n < 256) ? Vx[k*256 + n] : Vg[k*128 + (n - 256)];
        __nv_bfloat16 hb = __float2bfloat16(v);
        __nv_bfloat16* row = (__nv_bfloat16*)(smem + SB_B + n*HPITCH);
        row[k]      = hb;
        row[64 + k] = __float2bfloat16(v - __bfloat162float(hb));
    }
    // ---- zero both h buffers (incl. pad rows) ----
    for (int i = tid; i < 2*13056/4; i += P2_THREADS)
        ((u32*)(smem + SB_H0))[i] = 0;

    // B ldmatrix addresses: gate g -> rows 64g + 8w .. +7
    u32 rowB[6];
    #pragma unroll
    for (int g = 0; g < 6; g++)
        rowB[g] = sb + SB_B + (u32)(64*g + 8*w + (lane & 7))*HPITCH
                + (((lane >> 3) & 1) << 4);

    // row groups rg=0..4: (mi,hm) = (0,0),(0,1),(1,0),(1,1),(2,0); r=16mi+8hm+gid
    // valid rows: r < 36 (rg4 needs gid<4) AND rho < 5200
    int rrow[5], rhoA[5], gb[5], fb[5];
    bool vld[5];
    float cst0[5], cst1[5];
    #pragma unroll
    for (int rg = 0; rg < 5; rg++){
        int mi = rg >> 1, hm = rg & 1;
        int r = 16*mi + 8*hm + gid;
        rrow[rg] = r;
        int rho = blk*P2_R + r;
        vld[rg] = (r < P2_R) && (rho < NROWS);
        int rc = vld[rg] ? rho : (NROWS - 1);
        rhoA[rg] = rc;
        int b = rc / NN, n = rc - b*NN;
        gb[rg] = b*BSTRIDE + n*NH + hcol;
        fb[rg] = rc*NH + hcol;
        cst0[rg] = 0.0f; cst1[rg] = 0.0f;
    }
    __syncthreads();

    // ---- prefetch apre for t=0 ----
    float2 ap[5][6];
    #pragma unroll
    for (int rg = 0; rg < 5; rg++){
        const float* p = g_AG + (size_t)rhoA[rg]*384 + hcol;
        #pragma unroll
        for (int g = 0; g < 6; g++) ap[rg][g] = *(const float2*)(p + 64*g);
    }

    for (int t = 0; t < NT; t++){
        const u32 hin  = (t & 1) ? SB_H1 : SB_H0;
        const u32 hout = (t & 1) ? SB_H0 : SB_H1;

        // ---- acc init = apre (gate-aligned fragments); pad rows -> 0 ----
        float acc[3][6][4];
        #pragma unroll
        for (int mi = 0; mi < 3; mi++){
            #pragma unroll
            for (int g = 0; g < 6; g++){
                int rg0 = 2*mi, rg1 = 2*mi + 1;
                acc[mi][g][0] = ap[rg0][g].x;
                acc[mi][g][1] = ap[rg0][g].y;
                if (mi < 2){
                    acc[mi][g][2] = ap[rg1][g].x;
                    acc[mi][g][3] = ap[rg1][g].y;
                } else {
                    acc[mi][g][2] = 0.0f; acc[mi][g][3] = 0.0f;
                }
            }
        }

        // ---- prefetch apre for t+1 (hidden under MMA) ----
        if (t + 1 < NT){
            #pragma unroll
            for (int rg = 0; rg < 5; rg++){
                const float* p = g_AG + ((size_t)(t+1)*NROWS + rhoA[rg])*384 + hcol;
                #pragma unroll
                for (int g = 0; g < 6; g++) ap[rg][g] = *(const float2*)(p + 64*g);
            }
        }

        // ---- MMA: fused split-3 per kf ----
        u32 rowA[3];
        #pragma unroll
        for (int mi = 0; mi < 3; mi++)
            rowA[mi] = sb + hin + (u32)(16*mi + (lane & 15))*HPITCH + ((lane >> 4) << 4);

        #pragma unroll
        for (int kf = 0; kf < 4; kf++){
            u32 Ah[3][4], Al[3][4];
            #pragma unroll
            for (int mi = 0; mi < 3; mi++){
                ldsm_x4(Ah[mi][0],Ah[mi][1],Ah[mi][2],Ah[mi][3], rowA[mi] + kf*32);
                ldsm_x4(Al[mi][0],Al[mi][1],Al[mi][2],Al[mi][3], rowA[mi] + 128 + kf*32);
            }
            u32 Bh[6][2], Bl[6][2];
            #pragma unroll
            for (int g = 0; g < 6; g++){
                ldsm_x2(Bh[g][0], Bh[g][1], rowB[g] + kf*32);
                ldsm_x2(Bl[g][0], Bl[g][1], rowB[g] + 128 + kf*32);
            }
            #pragma unroll
            for (int g = 0; g < 6; g++)
                #pragma unroll
                for (int mi = 0; mi < 3; mi++){
                    mma16816(acc[mi][g], Ah[mi], Bh[g]);
                    mma16816(acc[mi][g], Ah[mi], Bl[g]);
                    mma16816(acc[mi][g], Al[mi], Bh[g]);
                }
        }

        // ---- EW fully in registers: 5 element-pairs per thread ----
        #pragma unroll
        for (int rg = 0; rg < 5; rg++){
            int mi = rg >> 1, hm = rg & 1;
            float gf0 = acc[mi][0][2*hm], gf1 = acc[mi][0][2*hm+1];
            float gi0 = acc[mi][1][2*hm], gi1 = acc[mi][1][2*hm+1];
            float go0 = acc[mi][2][2*hm], go1 = acc[mi][2][2*hm+1];
            float gu0 = acc[mi][3][2*hm], gu1 = acc[mi][3][2*hm+1];
            float gG0 = acc[mi][4][2*hm], gG1 = acc[mi][4][2*hm+1];
            float gV0 = acc[mi][5][2*hm], gV1 = acc[mi][5][2*hm+1];

            float hn0, hn1;
            {
                float ef = __expf(-gf0);
                float eg = __expf(-gG0);
                float fgf = __fdividef(1.0f, 1.0f + ef + eg + ef*eg);
                float ei = __expf(-gi0);
                float eu = __expf(-gu0);
                float ev = __expf(-gV0);
                float iuu = __fdividef(1.0f, (1.0f+ei)*(1.0f+eu)*(1.0f+ev));
                float c = fgf*cst0[rg] + iuu;
                cst0[rg] = c;
                float ot = __fdividef(1.0f, 1.0f + __expf(-go0));
                float th = 1.0f - __fdividef(2.0f, 1.0f + __expf(2.0f*c));
                hn0 = ot * th;
            }
            {
                float ef = __expf(-gf1);
                float eg = __expf(-gG1);
                float fgf = __fdividef(1.0f, 1.0f + ef + eg + ef*eg);
                float ei = __expf(-gi1);
                float eu = __expf(-gu1);
                float ev = __expf(-gV1);
                float iuu = __fdividef(1.0f, (1.0f+ei)*(1.0f+eu)*(1.0f+ev));
                float c = fgf*cst1[rg] + iuu;
                cst1[rg] = c;
                float ot = __fdividef(1.0f, 1.0f + __expf(-go1));
                float th = 1.0f - __fdividef(2.0f, 1.0f + __expf(2.0f*c));
                hn1 = ot * th;
            }

            // write h (hi/lo bf16) into hout (bounded even for invalid rows)
            u32 hhi = bfpack(hn0, hn1);
            float r0 = hn0 - __uint_as_float(hhi << 16);
            float r1 = hn1 - __uint_as_float(hhi & 0xFFFF0000u);
            u32 hlo = bfpack(r0, r1);
            *(u32*)(smem + hout + rrow[rg]*HPITCH + 4*hpi)       = hhi;
            *(u32*)(smem + hout + rrow[rg]*HPITCH + 128 + 4*hpi) = hlo;

            if (vld[rg]){
                float2 hv = make_float2(hn0, hn1);
                *(float2*)&hidden[gb[rg] + t*HSTRIDE] = hv;
                if (t == NT-1){
                    *(float2*)&htp[fb[rg]] = hv;
                    *(float2*)&ctp[fb[rg]] = make_float2(cst0[rg], cst1[rg]);
                }
            }
        }
        __syncthreads();   // h(t) published before step t+1 ldsm
    }
}

extern "C" void kernel_launch(void* const* d_in, const int* in_sizes, int n_in,
                              void* d_out, int out_size)
{
    const float* x   = (const float*)d_in[0];
    const float* o_s = (const float*)d_in[1];
    const float* Ux  = (const float*)d_in[2];
    const float* Vx  = (const float*)d_in[3];
    const float* bx  = (const float*)d_in[4];
    const float* Ug  = (const float*)d_in[5];
    const float* Vg  = (const float*)d_in[6];
    const float* bg  = (const float*)d_in[7];

    float* out    = (float*)d_out;
    float* hidden = out;                               // [B,T,N,H]
    float* htp    = out + (size_t)BTN * NH;            // [B,N,H]
    float* ctp    = htp + (size_t)NROWS * NH;          // [B,N,H]

    cudaFuncSetAttribute(glstm_pre_mma, cudaFuncAttributeMaxDynamicSharedMemorySize, P1_SMEM);
    cudaFuncSetAttribute(glstm_rec_mma, cudaFuncAttributeMaxDynamicSharedMemorySize, P2_SMEM);

    glstm_pre_mma<<<P1_GRID, P1_THREADS, P1_SMEM>>>(x, o_s, Ux, bx, Ug, bg);
    glstm_rec_mma<<<P2_BLOCKS, P2_THREADS, P2_SMEM>>>(Vx, Vg, hidden, htp, ctp);
}

// round 16
// speedup vs baseline: 1.2540x; 1.0535x over previous
#include <cuda_runtime.h>
#include <cuda_bf16.h>
#include <cstdint>

typedef unsigned long long u64;
typedef unsigned int u32;
typedef unsigned short u16;

#define NB 16
#define NT 96
#define NN 325
#define ND 64
#define NH 64
#define NROWS (NB*NN)          // 5200
#define BTN (NB*NT*NN)         // 499200
#define HSTRIDE (NN*NH)        // 20800
#define BSTRIDE (NT*NN*NH)     // 1996800

// Scratch: o-projection only: [t][row][128] (gf | gu), row = b*NN+n
__device__ float g_G[(size_t)BTN * 128];

// ================= helpers =================
__device__ __forceinline__ u32 smem_u32(const void* p){
    u32 a; asm("{ .reg .u64 t; cvta.to.shared.u64 t, %1; cvt.u32.u64 %0, t; }" : "=r"(a) : "l"(p));
    return a;
}
__device__ __forceinline__ u32 bfpack(float lo_elem, float hi_elem){
    u32 r; asm("cvt.rn.bf16x2.f32 %0, %1, %2;" : "=r"(r) : "f"(hi_elem), "f"(lo_elem));
    return r;
}
__device__ __forceinline__ void ldsm_x4(u32& a0,u32& a1,u32& a2,u32& a3, u32 addr){
    asm volatile("ldmatrix.sync.aligned.m8n8.x4.shared.b16 {%0,%1,%2,%3}, [%4];"
      : "=r"(a0),"=r"(a1),"=r"(a2),"=r"(a3) : "r"(addr));
}
__device__ __forceinline__ void ldsm_x2(u32& b0,u32& b1, u32 addr){
    asm volatile("ldmatrix.sync.aligned.m8n8.x2.shared.b16 {%0,%1}, [%2];"
      : "=r"(b0),"=r"(b1) : "r"(addr));
}
__device__ __forceinline__ void mma16816(float* c, const u32* a, const u32* b){
    asm volatile("mma.sync.aligned.m16n8k16.row.col.f32.bf16.bf16.f32 "
      "{%0,%1,%2,%3}, {%4,%5,%6,%7}, {%8,%9}, {%0,%1,%2,%3};"
      : "+f"(c[0]),"+f"(c[1]),"+f"(c[2]),"+f"(c[3])
      : "r"(a[0]),"r"(a[1]),"r"(a[2]),"r"(a[3]), "r"(b[0]),"r"(b[1]));
}

// =====================================================================
// Slim pre (HMMA): G = o_s @ Ug + bg  (N=128), split-3 bf16 (proven
// phase-1 structure, o-only). 64-row tiles, 256 threads, 8 warps x 16 cols.
// =====================================================================
#define Q_THREADS 256
#define Q_ROWS 64
#define Q_TILES (BTN/Q_ROWS)     // 7800
#define Q_GRID 148

#define QPITCH 400
#define QS_BIAS 0                // 128 f32 = 512
#define QS_B    512              // 128*400 = 51200
#define QS_A    51712            // 64*400 = 25600
#define Q_SMEM  77312

__global__ void __launch_bounds__(Q_THREADS, 1)
glstm_pre_g(const float* __restrict__ osrc, const float* __restrict__ Ug,
            const float* __restrict__ bg)
{
    extern __shared__ unsigned char smem[];
    float* bias_s = (float*)(smem + QS_BIAS);
    const int tid = threadIdx.x;
    const int w   = tid >> 5;
    const int lane = tid & 31;
    const int gid = lane >> 2, tid4 = lane & 3;

    if (tid < 128) bias_s[tid] = bg[tid];

    // B' = [Whi | Wlo | Whi] rows n=0..127
    for (int i = tid; i < 64*128; i += Q_THREADS){
        int n = i & 127, k = i >> 7;
        float v = Ug[k*128 + n];
        __nv_bfloat16 hb = __float2bfloat16(v);
        float lo = v - __bfloat162float(hb);
        __nv_bfloat16* row = (__nv_bfloat16*)(smem + QS_B + n*QPITCH);
        row[k] = hb; row[128 + k] = hb;
        row[64 + k] = __float2bfloat16(lo);
    }

    const u32 sb = smem_u32(smem);
    u32 rowAo[4];
    #pragma unroll
    for (int mi = 0; mi < 4; mi++)
        rowAo[mi] = sb + QS_A + (u32)(16*mi + (lane & 15))*QPITCH + ((lane >> 4) << 4);
    u32 rowB[2];
    #pragma unroll
    for (int ni = 0; ni < 2; ni++)
        rowB[ni] = sb + QS_B + (u32)(16*w + 8*ni + (lane & 7))*QPITCH + (((lane >> 3) & 1) << 4);

    const int cr = tid >> 2, ck0 = (tid & 3) << 4;
    u32* ao32 = (u32*)(smem + QS_A + cr*QPITCH);

    int tile = blockIdx.x;
    float4 ov[4];
    {
        const float4* op = (const float4*)(osrc + (size_t)((long long)tile*Q_ROWS + cr)*64 + ck0);
        #pragma unroll
        for (int j = 0; j < 4; j++) ov[j] = op[j];
    }

    while (tile < Q_TILES){
        const long long m0 = (long long)tile * Q_ROWS;

        #pragma unroll
        for (int j = 0; j < 4; j++){
            #pragma unroll
            for (int h = 0; h < 2; h++){
                float a = h ? ov[j].z : ov[j].x;
                float b = h ? ov[j].w : ov[j].y;
                int k = ck0 + 4*j + 2*h;
                u32 hp = bfpack(a, b);
                float ra = a - __uint_as_float(hp << 16);
                float rb = b - __uint_as_float(hp & 0xFFFF0000u);
                u32 lp = bfpack(ra, rb);
                ao32[k>>1] = hp; ao32[32 + (k>>1)] = hp; ao32[64 + (k>>1)] = lp;
            }
        }
        __syncthreads();

        const int nxt = tile + gridDim.x;
        if (nxt < Q_TILES){
            const float4* op = (const float4*)(osrc + (size_t)((long long)nxt*Q_ROWS + cr)*64 + ck0);
            #pragma unroll
            for (int j = 0; j < 4; j++) ov[j] = op[j];
        }

        float acc[4][2][4];
        #pragma unroll
        for (int mi = 0; mi < 4; mi++)
            #pragma unroll
            for (int ni = 0; ni < 2; ni++)
                #pragma unroll
                for (int e = 0; e < 4; e++) acc[mi][ni][e] = 0.0f;

        #pragma unroll
        for (int kf = 0; kf < 12; kf++){
            u32 Aof[4][4];
            #pragma unroll
            for (int mi = 0; mi < 4; mi++)
                ldsm_x4(Aof[mi][0],Aof[mi][1],Aof[mi][2],Aof[mi][3], rowAo[mi] + kf*32);
            u32 Bf[2][2];
            #pragma unroll
            for (int ni = 0; ni < 2; ni++)
                ldsm_x2(Bf[ni][0], Bf[ni][1], rowB[ni] + kf*32);
            #pragma unroll
            for (int ni = 0; ni < 2; ni++)
                #pragma unroll
                for (int mi = 0; mi < 4; mi++)
                    mma16816(acc[mi][ni], Aof[mi], Bf[ni]);
        }
        __syncthreads();

        #pragma unroll
        for (int mi = 0; mi < 4; mi++){
            #pragma unroll
            for (int half = 0; half < 2; half++){
                int r = 16*mi + gid + 8*half;
                long long m = m0 + r;
                u32 mu = (u32)m;
                u32 qq = mu / NN;
                u32 n  = mu - qq*NN;
                u32 t  = qq % NT, b = qq / NT;
                size_t ro = (size_t)t*NROWS + (size_t)b*NN + n;
                float* pG = g_G + ro*128;
                #pragma unroll
                for (int ni = 0; ni < 2; ni++){
                    int col = 16*w + 8*ni + 2*tid4;
                    float2 bv = *(const float2*)&bias_s[col];
                    float2 cv;
                    cv.x = acc[mi][ni][half*2 + 0] + bv.x;
                    cv.y = acc[mi][ni][half*2 + 1] + bv.y;
                    *(float2*)(pG + col) = cv;
                }
            }
        }
        tile = nxt;
    }
}

// =====================================================================
// Fused rec (HMMA): gates = x@Ux + bx (fused) + h@[Vx|Vg] + (o@Ug+bg from
// g_G). 130 blocks x 40 rows, gate-aligned fragments, EW in-register.
// Single x/h buffers; TWO __syncthreads per step.
// RACE FIX: barrier between init-zero and t=0 x conversion.
// =====================================================================
#define P2_THREADS 256
#define P2_R 40
#define P2_BLOCKS 130
#define HPITCH 272                   // bytes per row (hi 128 | lo 128 + pad)
#define SB_V 0                       // 384*272 = 104448
#define SB_U 104448                  // 256*272 = 69632
#define SB_X 174080                  // 48*272 = 13056
#define SB_H 187136                  // 48*272 = 13056
#define P2_SMEM 200192

__global__ void __launch_bounds__(P2_THREADS, 1)
glstm_rec_fused(const float* __restrict__ x, const float* __restrict__ Ux,
                const float* __restrict__ bx,
                const float* __restrict__ Vx, const float* __restrict__ Vg,
                float* __restrict__ hidden, float* __restrict__ htp,
                float* __restrict__ ctp)
{
    extern __shared__ unsigned char smem[];
    const u32 sb = smem_u32(smem);

    const int tid  = threadIdx.x;
    const int lane = tid & 31;
    const int w    = tid >> 5;      // 0..7
    const int gid  = lane >> 2, tid4 = lane & 3;
    const int blk  = blockIdx.x;
    const int hcol = 8*w + 2*tid4;  // column pair owned by this thread
    const int hpi  = 4*w + tid4;

    // ---- build B_V = [Vx | Vg] rows 0..383 as [hi|lo] bf16 ----
    for (int i = tid; i < 64*384; i += P2_THREADS){
        int k = i / 384, n = i - k*384;
        float v = (n < 256) ? Vx[k*256 + n] : Vg[k*128 + (n - 256)];
        __nv_bfloat16 hb = __float2bfloat16(v);
        __nv_bfloat16* row = (__nv_bfloat16*)(smem + SB_V + n*HPITCH);
        row[k]      = hb;
        row[64 + k] = __float2bfloat16(v - __bfloat162float(hb));
    }
    // ---- build B_U = Ux rows 0..255 as [hi|lo] bf16 ----
    for (int i = tid; i < 64*256; i += P2_THREADS){
        int k = i >> 8, n = i & 255;
        float v = Ux[k*256 + n];
        __nv_bfloat16 hb = __float2bfloat16(v);
        __nv_bfloat16* row = (__nv_bfloat16*)(smem + SB_U + n*HPITCH);
        row[k]      = hb;
        row[64 + k] = __float2bfloat16(v - __bfloat162float(hb));
    }
    // ---- zero x and h buffers (incl. pad rows) ----
    for (int i = tid; i < 2*13056/4; i += P2_THREADS)
        ((u32*)(smem + SB_X))[i] = 0;

    // B ldmatrix addresses
    u32 rowBV[6], rowBU[4];
    #pragma unroll
    for (int g = 0; g < 6; g++)
        rowBV[g] = sb + SB_V + (u32)(64*g + 8*w + (lane & 7))*HPITCH
                 + (((lane >> 3) & 1) << 4);
    #pragma unroll
    for (int g = 0; g < 4; g++)
        rowBU[g] = sb + SB_U + (u32)(64*g + 8*w + (lane & 7))*HPITCH
                 + (((lane >> 3) & 1) << 4);

    u32 rowAh[3], rowAx[3];
    #pragma unroll
    for (int mi = 0; mi < 3; mi++){
        u32 off = (u32)(16*mi + (lane & 15))*HPITCH + ((lane >> 4) << 4);
        rowAh[mi] = sb + SB_H + off;
        rowAx[mi] = sb + SB_X + off;
    }

    // bias bx for gates 0..3 at this thread's column pair
    float2 bxv[4];
    #pragma unroll
    for (int g = 0; g < 4; g++) bxv[g] = *(const float2*)&bx[64*g + hcol];

    // row groups rg=0..4: (mi,hm)=(0,0),(0,1),(1,0),(1,1),(2,0); r=16mi+8hm+gid
    int rrow[5], rhoA[5], gb[5], fb[5];
    float cst0[5], cst1[5];
    #pragma unroll
    for (int rg = 0; rg < 5; rg++){
        int mi = rg >> 1, hm = rg & 1;
        int r = 16*mi + 8*hm + gid;
        rrow[rg] = r;
        int rho = blk*P2_R + r;              // < 5200 always
        rhoA[rg] = rho;
        int b = rho / NN, n = rho - b*NN;
        gb[rg] = b*BSTRIDE + n*NH + hcol;
        fb[rg] = rho*NH + hcol;
        cst0[rg] = 0.0f; cst1[rg] = 0.0f;
    }

    // x element ownership: 10 elems, i = tid + 256j -> row=i>>6, k=i&63
    int xoff[10];
    #pragma unroll
    for (int j = 0; j < 10; j++){
        int i = tid + j*P2_THREADS;
        int row = i >> 6, k = i & 63;
        int rho = blk*P2_R + row;
        int b = rho / NN, n = rho - b*NN;
        xoff[j] = b*BSTRIDE + n*64 + k;
    }

    __syncthreads();   // RACE FIX: zero-fill visible before x(t=0) conversion

    // ---- load + convert x(t=0); prefetch oap(t=0) ----
    float xv[10];
    #pragma unroll
    for (int j = 0; j < 10; j++) xv[j] = x[xoff[j]];
    #pragma unroll
    for (int j = 0; j < 10; j++){
        int i = tid + j*P2_THREADS;
        int row = i >> 6, k = i & 63;
        __nv_bfloat16 hb = __float2bfloat16(xv[j]);
        *(u16*)(smem + SB_X + row*HPITCH + 2*k) = __bfloat16_as_ushort(hb);
        *(u16*)(smem + SB_X + row*HPITCH + 128 + 2*k) =
            __bfloat16_as_ushort(__float2bfloat16(xv[j] - __bfloat162float(hb)));
    }
    float2 oap[5][2];
    #pragma unroll
    for (int rg = 0; rg < 5; rg++){
        const float* p = g_G + (size_t)rhoA[rg]*128 + hcol;
        oap[rg][0] = *(const float2*)(p);
        oap[rg][1] = *(const float2*)(p + 64);
    }
    __syncthreads();

    for (int t = 0; t < NT; t++){
        // ---- acc init: g<4 -> bx; g=4,5 -> oap; pad zeros ----
        float acc[3][6][4];
        #pragma unroll
        for (int mi = 0; mi < 3; mi++){
            #pragma unroll
            for (int g = 0; g < 4; g++){
                acc[mi][g][0] = bxv[g].x; acc[mi][g][1] = bxv[g].y;
                acc[mi][g][2] = bxv[g].x; acc[mi][g][3] = bxv[g].y;
            }
            int rg0 = 2*mi, rg1 = 2*mi + 1;
            #pragma unroll
            for (int g = 4; g < 6; g++){
                acc[mi][g][0] = oap[rg0][g-4].x; acc[mi][g][1] = oap[rg0][g-4].y;
                if (mi < 2){
                    acc[mi][g][2] = oap[rg1][g-4].x; acc[mi][g][3] = oap[rg1][g-4].y;
                } else { acc[mi][g][2] = 0.0f; acc[mi][g][3] = 0.0f; }
            }
        }

        // ---- prefetch x(t+1), oap(t+1) (hidden under MMA) ----
        if (t + 1 < NT){
            #pragma unroll
            for (int j = 0; j < 10; j++) xv[j] = x[xoff[j] + (t+1)*HSTRIDE];
            #pragma unroll
            for (int rg = 0; rg < 5; rg++){
                const float* p = g_G + ((size_t)(t+1)*NROWS + rhoA[rg])*128 + hcol;
                oap[rg][0] = *(const float2*)(p);
                oap[rg][1] = *(const float2*)(p + 64);
            }
        }

        // ---- MMA per kf: x@Ux (gates 0-3) then h@V (gates 0-5) ----
        #pragma unroll
        for (int kf = 0; kf < 4; kf++){
            {   // x part
                u32 Xh[3][4], Xl[3][4];
                #pragma unroll
                for (int mi = 0; mi < 3; mi++){
                    ldsm_x4(Xh[mi][0],Xh[mi][1],Xh[mi][2],Xh[mi][3], rowAx[mi] + kf*32);
                    ldsm_x4(Xl[mi][0],Xl[mi][1],Xl[mi][2],Xl[mi][3], rowAx[mi] + 128 + kf*32);
                }
                u32 Uh[4][2], Ul[4][2];
                #pragma unroll
                for (int g = 0; g < 4; g++){
                    ldsm_x2(Uh[g][0], Uh[g][1], rowBU[g] + kf*32);
                    ldsm_x2(Ul[g][0], Ul[g][1], rowBU[g] + 128 + kf*32);
                }
                #pragma unroll
                for (int g = 0; g < 4; g++)
                    #pragma unroll
                    for (int mi = 0; mi < 3; mi++){
                        mma16816(acc[mi][g], Xh[mi], Uh[g]);
                        mma16816(acc[mi][g], Xh[mi], Ul[g]);
                        mma16816(acc[mi][g], Xl[mi], Uh[g]);
                    }
            }
            {   // h part
                u32 Hh[3][4], Hl[3][4];
                #pragma unroll
                for (int mi = 0; mi < 3; mi++){
                    ldsm_x4(Hh[mi][0],Hh[mi][1],Hh[mi][2],Hh[mi][3], rowAh[mi] + kf*32);
                    ldsm_x4(Hl[mi][0],Hl[mi][1],Hl[mi][2],Hl[mi][3], rowAh[mi] + 128 + kf*32);
                }
                u32 Vh[6][2], Vl[6][2];
                #pragma unroll
                for (int g = 0; g < 6; g++){
                    ldsm_x2(Vh[g][0], Vh[g][1], rowBV[g] + kf*32);
                    ldsm_x2(Vl[g][0], Vl[g][1], rowBV[g] + 128 + kf*32);
                }
                #pragma unroll
                for (int g = 0; g < 6; g++)
                    #pragma unroll
                    for (int mi = 0; mi < 3; mi++){
                        mma16816(acc[mi][g], Hh[mi], Vh[g]);
                        mma16816(acc[mi][g], Hh[mi], Vl[g]);
                        mma16816(acc[mi][g], Hl[mi], Vh[g]);
                    }
            }
        }
        __syncthreads();   // all reads of h(t-1), x_a(t) done

        // ---- convert x(t+1) into x_a ----
        if (t + 1 < NT){
            #pragma unroll
            for (int j = 0; j < 10; j++){
                int i = tid + j*P2_THREADS;
                int row = i >> 6, k = i & 63;
                __nv_bfloat16 hb = __float2bfloat16(xv[j]);
                *(u16*)(smem + SB_X + row*HPITCH + 2*k) = __bfloat16_as_ushort(hb);
                *(u16*)(smem + SB_X + row*HPITCH + 128 + 2*k) =
                    __bfloat16_as_ushort(__float2bfloat16(xv[j] - __bfloat162float(hb)));
            }
        }

        // ---- EW in registers: 5 element-pairs ----
        #pragma unroll
        for (int rg = 0; rg < 5; rg++){
            int mi = rg >> 1, hm = rg & 1;
            float gf0 = acc[mi][0][2*hm], gf1 = acc[mi][0][2*hm+1];
            float gi0 = acc[mi][1][2*hm], gi1 = acc[mi][1][2*hm+1];
            float go0 = acc[mi][2][2*hm], go1 = acc[mi][2][2*hm+1];
            float gu0 = acc[mi][3][2*hm], gu1 = acc[mi][3][2*hm+1];
            float gG0 = acc[mi][4][2*hm], gG1 = acc[mi][4][2*hm+1];
            float gV0 = acc[mi][5][2*hm], gV1 = acc[mi][5][2*hm+1];

            float hn0, hn1;
            {
                float ef = __expf(-gf0);
                float eg = __expf(-gG0);
                float fgf = __fdividef(1.0f, 1.0f + ef + eg + ef*eg);
                float ei = __expf(-gi0);
                float eu = __expf(-gu0);
                float ev = __expf(-gV0);
                float iuu = __fdividef(1.0f, (1.0f+ei)*(1.0f+eu)*(1.0f+ev));
                float c = fgf*cst0[rg] + iuu;
                cst0[rg] = c;
                float ot = __fdividef(1.0f, 1.0f + __expf(-go0));
                float th = 1.0f - __fdividef(2.0f, 1.0f + __expf(2.0f*c));
                hn0 = ot * th;
            }
            {
                float ef = __expf(-gf1);
                float eg = __expf(-gG1);
                float fgf = __fdividef(1.0f, 1.0f + ef + eg + ef*eg);
                float ei = __expf(-gi1);
                float eu = __expf(-gu1);
                float ev = __expf(-gV1);
                float iuu = __fdividef(1.0f, (1.0f+ei)*(1.0f+eu)*(1.0f+ev));
                float c = fgf*cst1[rg] + iuu;
                cst1[rg] = c;
                float ot = __fdividef(1.0f, 1.0f + __expf(-go1));
                float th = 1.0f - __fdividef(2.0f, 1.0f + __expf(2.0f*c));
                hn1 = ot * th;
            }

            u32 hhi = bfpack(hn0, hn1);
            float r0 = hn0 - __uint_as_float(hhi << 16);
            float r1 = hn1 - __uint_as_float(hhi & 0xFFFF0000u);
            u32 hlo = bfpack(r0, r1);
            *(u32*)(smem + SB_H + rrow[rg]*HPITCH + 4*hpi)       = hhi;
            *(u32*)(smem + SB_H + rrow[rg]*HPITCH + 128 + 4*hpi) = hlo;

            float2 hv = make_float2(hn0, hn1);
            *(float2*)&hidden[gb[rg] + t*HSTRIDE] = hv;
            if (t == NT-1){
                *(float2*)&htp[fb[rg]] = hv;
                *(float2*)&ctp[fb[rg]] = make_float2(cst0[rg], cst1[rg]);
            }
        }
        __syncthreads();   // h(t) + x_a(t+1) published
    }
}

extern "C" void kernel_launch(void* const* d_in, const int* in_sizes, int n_in,
                              void* d_out, int out_size)
{
    const float* x   = (const float*)d_in[0];
    const float* o_s = (const float*)d_in[1];
    const float* Ux  = (const float*)d_in[2];
    const float* Vx  = (const float*)d_in[3];
    const float* bx  = (const float*)d_in[4];
    const float* Ug  = (const float*)d_in[5];
    const float* Vg  = (const float*)d_in[6];
    const float* bg  = (const float*)d_in[7];

    float* out    = (float*)d_out;
    float* hidden = out;                               // [B,T,N,H]
    float* htp    = out + (size_t)BTN * NH;            // [B,N,H]
    float* ctp    = htp + (size_t)NROWS * NH;          // [B,N,H]

    cudaFuncSetAttribute(glstm_pre_g,     cudaFuncAttributeMaxDynamicSharedMemorySize, Q_SMEM);
    cudaFuncSetAttribute(glstm_rec_fused, cudaFuncAttributeMaxDynamicSharedMemorySize, P2_SMEM);

    glstm_pre_g<<<Q_GRID, Q_THREADS, Q_SMEM>>>(o_s, Ug, bg);
    glstm_rec_fused<<<P2_BLOCKS, P2_THREADS, P2_SMEM>>>(x, Ux, bx, Vx, Vg,
                                                        hidden, htp, ctp);
}

// round 17
// speedup vs baseline: 1.3191x; 1.0519x over previous
#include <cuda_runtime.h>
#include <cuda_bf16.h>
#include <cstdint>

typedef unsigned long long u64;
typedef unsigned int u32;
typedef unsigned short u16;

#define NB 16
#define NT 96
#define NN 325
#define ND 64
#define NH 64
#define NROWS (NB*NN)          // 5200
#define BTN (NB*NT*NN)         // 499200
#define HSTRIDE (NN*NH)        // 20800
#define BSTRIDE (NT*NN*NH)     // 1996800

// Scratch: o-projection only: [t][row][128] (gf | gu), row = b*NN+n
__device__ float g_G[(size_t)BTN * 128];

// ================= helpers =================
__device__ __forceinline__ u32 smem_u32(const void* p){
    u32 a; asm("{ .reg .u64 t; cvta.to.shared.u64 t, %1; cvt.u32.u64 %0, t; }" : "=r"(a) : "l"(p));
    return a;
}
__device__ __forceinline__ u32 bfpack(float lo_elem, float hi_elem){
    u32 r; asm("cvt.rn.bf16x2.f32 %0, %1, %2;" : "=r"(r) : "f"(hi_elem), "f"(lo_elem));
    return r;
}
__device__ __forceinline__ void ldsm_x4(u32& a0,u32& a1,u32& a2,u32& a3, u32 addr){
    asm volatile("ldmatrix.sync.aligned.m8n8.x4.shared.b16 {%0,%1,%2,%3}, [%4];"
      : "=r"(a0),"=r"(a1),"=r"(a2),"=r"(a3) : "r"(addr));
}
__device__ __forceinline__ void ldsm_x2(u32& b0,u32& b1, u32 addr){
    asm volatile("ldmatrix.sync.aligned.m8n8.x2.shared.b16 {%0,%1}, [%2];"
      : "=r"(b0),"=r"(b1) : "r"(addr));
}
__device__ __forceinline__ void mma16816(float* c, const u32* a, const u32* b){
    asm volatile("mma.sync.aligned.m16n8k16.row.col.f32.bf16.bf16.f32 "
      "{%0,%1,%2,%3}, {%4,%5,%6,%7}, {%8,%9}, {%0,%1,%2,%3};"
      : "+f"(c[0]),"+f"(c[1]),"+f"(c[2]),"+f"(c[3])
      : "r"(a[0]),"r"(a[1]),"r"(a[2]),"r"(a[3]), "r"(b[0]),"r"(b[1]));
}
#define CP_ASYNC8(dst, src) asm volatile("cp.async.ca.shared.global [%0], [%1], 8;" :: "r"(dst), "l"(src) : "memory")
#define CP_COMMIT() asm volatile("cp.async.commit_group;" ::: "memory")
#define CP_WAIT0()  asm volatile("cp.async.wait_group 0;" ::: "memory")

// =====================================================================
// Slim pre (HMMA): G = o_s @ Ug + bg  (N=128), split-3 bf16.
// 64-row tiles, 256 threads, 8 warps x 16 cols. (proven R16)
// =====================================================================
#define Q_THREADS 256
#define Q_ROWS 64
#define Q_TILES (BTN/Q_ROWS)     // 7800
#define Q_GRID 148

#define QPITCH 400
#define QS_BIAS 0                // 128 f32 = 512
#define QS_B    512              // 128*400 = 51200
#define QS_A    51712            // 64*400 = 25600
#define Q_SMEM  77312

__global__ void __launch_bounds__(Q_THREADS, 1)
glstm_pre_g(const float* __restrict__ osrc, const float* __restrict__ Ug,
            const float* __restrict__ bg)
{
    extern __shared__ unsigned char smem[];
    float* bias_s = (float*)(smem + QS_BIAS);
    const int tid = threadIdx.x;
    const int w   = tid >> 5;
    const int lane = tid & 31;
    const int gid = lane >> 2, tid4 = lane & 3;

    if (tid < 128) bias_s[tid] = bg[tid];

    for (int i = tid; i < 64*128; i += Q_THREADS){
        int n = i & 127, k = i >> 7;
        float v = Ug[k*128 + n];
        __nv_bfloat16 hb = __float2bfloat16(v);
        float lo = v - __bfloat162float(hb);
        __nv_bfloat16* row = (__nv_bfloat16*)(smem + QS_B + n*QPITCH);
        row[k] = hb; row[128 + k] = hb;
        row[64 + k] = __float2bfloat16(lo);
    }

    const u32 sb = smem_u32(smem);
    u32 rowAo[4];
    #pragma unroll
    for (int mi = 0; mi < 4; mi++)
        rowAo[mi] = sb + QS_A + (u32)(16*mi + (lane & 15))*QPITCH + ((lane >> 4) << 4);
    u32 rowB[2];
    #pragma unroll
    for (int ni = 0; ni < 2; ni++)
        rowB[ni] = sb + QS_B + (u32)(16*w + 8*ni + (lane & 7))*QPITCH + (((lane >> 3) & 1) << 4);

    const int cr = tid >> 2, ck0 = (tid & 3) << 4;
    u32* ao32 = (u32*)(smem + QS_A + cr*QPITCH);

    int tile = blockIdx.x;
    float4 ov[4];
    {
        const float4* op = (const float4*)(osrc + (size_t)((long long)tile*Q_ROWS + cr)*64 + ck0);
        #pragma unroll
        for (int j = 0; j < 4; j++) ov[j] = op[j];
    }

    while (tile < Q_TILES){
        const long long m0 = (long long)tile * Q_ROWS;

        #pragma unroll
        for (int j = 0; j < 4; j++){
            #pragma unroll
            for (int h = 0; h < 2; h++){
                float a = h ? ov[j].z : ov[j].x;
                float b = h ? ov[j].w : ov[j].y;
                int k = ck0 + 4*j + 2*h;
                u32 hp = bfpack(a, b);
                float ra = a - __uint_as_float(hp << 16);
                float rb = b - __uint_as_float(hp & 0xFFFF0000u);
                u32 lp = bfpack(ra, rb);
                ao32[k>>1] = hp; ao32[32 + (k>>1)] = hp; ao32[64 + (k>>1)] = lp;
            }
        }
        __syncthreads();

        const int nxt = tile + gridDim.x;
        if (nxt < Q_TILES){
            const float4* op = (const float4*)(osrc + (size_t)((long long)nxt*Q_ROWS + cr)*64 + ck0);
            #pragma unroll
            for (int j = 0; j < 4; j++) ov[j] = op[j];
        }

        float acc[4][2][4];
        #pragma unroll
        for (int mi = 0; mi < 4; mi++)
            #pragma unroll
            for (int ni = 0; ni < 2; ni++)
                #pragma unroll
                for (int e = 0; e < 4; e++) acc[mi][ni][e] = 0.0f;

        #pragma unroll
        for (int kf = 0; kf < 12; kf++){
            u32 Aof[4][4];
            #pragma unroll
            for (int mi = 0; mi < 4; mi++)
                ldsm_x4(Aof[mi][0],Aof[mi][1],Aof[mi][2],Aof[mi][3], rowAo[mi] + kf*32);
            u32 Bf[2][2];
            #pragma unroll
            for (int ni = 0; ni < 2; ni++)
                ldsm_x2(Bf[ni][0], Bf[ni][1], rowB[ni] + kf*32);
            #pragma unroll
            for (int ni = 0; ni < 2; ni++)
                #pragma unroll
                for (int mi = 0; mi < 4; mi++)
                    mma16816(acc[mi][ni], Aof[mi], Bf[ni]);
        }
        __syncthreads();

        #pragma unroll
        for (int mi = 0; mi < 4; mi++){
            #pragma unroll
            for (int half = 0; half < 2; half++){
                int r = 16*mi + gid + 8*half;
                long long m = m0 + r;
                u32 mu = (u32)m;
                u32 qq = mu / NN;
                u32 n  = mu - qq*NN;
                u32 t  = qq % NT, b = qq / NT;
                size_t ro = (size_t)t*NROWS + (size_t)b*NN + n;
                float* pG = g_G + ro*128;
                #pragma unroll
                for (int ni = 0; ni < 2; ni++){
                    int col = 16*w + 8*ni + 2*tid4;
                    float2 bv = *(const float2*)&bias_s[col];
                    float2 cv;
                    cv.x = acc[mi][ni][half*2 + 0] + bv.x;
                    cv.y = acc[mi][ni][half*2 + 1] + bv.y;
                    *(float2*)(pG + col) = cv;
                }
            }
        }
        tile = nxt;
    }
}

// =====================================================================
// Fused rec (HMMA): gates = x@Ux + bx (fused) + h@[Vx|Vg] + (o@Ug+bg from
// g_G via cp.async self-staging). 130 blocks x 40 rows, gate-aligned
// fragments, EW in-register. TWO __syncthreads per step.
// =====================================================================
#define P2_THREADS 256
#define P2_R 40
#define P2_BLOCKS 130
#define HPITCH 272                   // bytes per row (hi 128 | lo 128 + pad)
#define SB_V  0                      // 384*272 = 104448
#define SB_U  104448                 // 256*272 = 69632
#define SB_X  174080                 // 48*272 = 13056
#define SB_H  187136                 // 48*272 = 13056
#define SB_OS 200192                 // oap staging [10][256] float2 = 20480
#define P2_SMEM 220672

__global__ void __launch_bounds__(P2_THREADS, 1)
glstm_rec_fused(const float* __restrict__ x, const float* __restrict__ Ux,
                const float* __restrict__ bx,
                const float* __restrict__ Vx, const float* __restrict__ Vg,
                float* __restrict__ hidden, float* __restrict__ htp,
                float* __restrict__ ctp)
{
    extern __shared__ unsigned char smem[];
    const u32 sb = smem_u32(smem);

    const int tid  = threadIdx.x;
    const int lane = tid & 31;
    const int w    = tid >> 5;      // 0..7
    const int gid  = lane >> 2, tid4 = lane & 3;
    const int blk  = blockIdx.x;
    const int hcol = 8*w + 2*tid4;  // column pair owned by this thread
    const int hpi  = 4*w + tid4;

    // ---- build B_V = [Vx | Vg] rows 0..383 as [hi|lo] bf16 ----
    for (int i = tid; i < 64*384; i += P2_THREADS){
        int k = i / 384, n = i - k*384;
        float v = (n < 256) ? Vx[k*256 + n] : Vg[k*128 + (n - 256)];
        __nv_bfloat16 hb = __float2bfloat16(v);
        __nv_bfloat16* row = (__nv_bfloat16*)(smem + SB_V + n*HPITCH);
        row[k]      = hb;
        row[64 + k] = __float2bfloat16(v - __bfloat162float(hb));
    }
    // ---- build B_U = Ux rows 0..255 as [hi|lo] bf16 ----
    for (int i = tid; i < 64*256; i += P2_THREADS){
        int k = i >> 8, n = i & 255;
        float v = Ux[k*256 + n];
        __nv_bfloat16 hb = __float2bfloat16(v);
        __nv_bfloat16* row = (__nv_bfloat16*)(smem + SB_U + n*HPITCH);
        row[k]      = hb;
        row[64 + k] = __float2bfloat16(v - __bfloat162float(hb));
    }
    // ---- zero x and h buffers (incl. pad rows) ----
    for (int i = tid; i < 2*13056/4; i += P2_THREADS)
        ((u32*)(smem + SB_X))[i] = 0;

    // B ldmatrix addresses
    u32 rowBV[6], rowBU[4];
    #pragma unroll
    for (int g = 0; g < 6; g++)
        rowBV[g] = sb + SB_V + (u32)(64*g + 8*w + (lane & 7))*HPITCH
                 + (((lane >> 3) & 1) << 4);
    #pragma unroll
    for (int g = 0; g < 4; g++)
        rowBU[g] = sb + SB_U + (u32)(64*g + 8*w + (lane & 7))*HPITCH
                 + (((lane >> 3) & 1) << 4);

    u32 rowAh[3], rowAx[3];
    #pragma unroll
    for (int mi = 0; mi < 3; mi++){
        u32 off = (u32)(16*mi + (lane & 15))*HPITCH + ((lane >> 4) << 4);
        rowAh[mi] = sb + SB_H + off;
        rowAx[mi] = sb + SB_X + off;
    }

    // bias bx for gates 0..3 at this thread's column pair
    float2 bxv[4];
    #pragma unroll
    for (int g = 0; g < 4; g++) bxv[g] = *(const float2*)&bx[64*g + hcol];

    // row groups rg=0..4: (mi,hm)=(0,0),(0,1),(1,0),(1,1),(2,0); r=16mi+8hm+gid
    int rrow[5], rhoA[5], gb[5], fb[5];
    float cst0[5], cst1[5];
    #pragma unroll
    for (int rg = 0; rg < 5; rg++){
        int mi = rg >> 1, hm = rg & 1;
        int r = 16*mi + 8*hm + gid;
        rrow[rg] = r;
        int rho = blk*P2_R + r;              // < 5200 always
        rhoA[rg] = rho;
        int b = rho / NN, n = rho - b*NN;
        gb[rg] = b*BSTRIDE + n*NH + hcol;
        fb[rg] = rho*NH + hcol;
        cst0[rg] = 0.0f; cst1[rg] = 0.0f;
    }

    // x element ownership: 10 elems, i = tid + 256j -> row=i>>6, k=i&63
    int xoff[10];
    #pragma unroll
    for (int j = 0; j < 10; j++){
        int i = tid + j*P2_THREADS;
        int row = i >> 6, k = i & 63;
        int rho = blk*P2_R + row;
        int b = rho / NN, n = rho - b*NN;
        xoff[j] = b*BSTRIDE + n*64 + k;
    }

    __syncthreads();   // zero-fill visible before x(t=0) conversion

    // ---- load + convert x(t=0) ----
    float xv[10];
    #pragma unroll
    for (int j = 0; j < 10; j++) xv[j] = x[xoff[j]];
    #pragma unroll
    for (int j = 0; j < 10; j++){
        int i = tid + j*P2_THREADS;
        int row = i >> 6, k = i & 63;
        __nv_bfloat16 hb = __float2bfloat16(xv[j]);
        *(u16*)(smem + SB_X + row*HPITCH + 2*k) = __bfloat16_as_ushort(hb);
        *(u16*)(smem + SB_X + row*HPITCH + 128 + 2*k) =
            __bfloat16_as_ushort(__float2bfloat16(xv[j] - __bfloat162float(hb)));
    }
    // ---- stage oap(t=0) via cp.async (self-owned slots [rg*2+gg][tid]) ----
    #pragma unroll
    for (int rg = 0; rg < 5; rg++){
        const float* p = g_G + (size_t)rhoA[rg]*128 + hcol;
        CP_ASYNC8(sb + SB_OS + (u32)((rg*2 + 0)*256 + tid)*8, p);
        CP_ASYNC8(sb + SB_OS + (u32)((rg*2 + 1)*256 + tid)*8, p + 64);
    }
    CP_COMMIT();
    __syncthreads();

    const float2* osg = (const float2*)(smem + SB_OS);

    for (int t = 0; t < NT; t++){
        CP_WAIT0();   // this step's oap slab landed (self-written slots)

        // ---- acc init: g<4 -> bx; g=4,5 -> staged oap; pad zeros ----
        float acc[3][6][4];
        #pragma unroll
        for (int mi = 0; mi < 3; mi++){
            #pragma unroll
            for (int g = 0; g < 4; g++){
                acc[mi][g][0] = bxv[g].x; acc[mi][g][1] = bxv[g].y;
                acc[mi][g][2] = bxv[g].x; acc[mi][g][3] = bxv[g].y;
            }
            int rg0 = 2*mi, rg1 = 2*mi + 1;
            #pragma unroll
            for (int g = 4; g < 6; g++){
                float2 a0 = osg[(rg0*2 + (g-4))*256 + tid];
                acc[mi][g][0] = a0.x; acc[mi][g][1] = a0.y;
                if (mi < 2){
                    float2 a1 = osg[(rg1*2 + (g-4))*256 + tid];
                    acc[mi][g][2] = a1.x; acc[mi][g][3] = a1.y;
                } else { acc[mi][g][2] = 0.0f; acc[mi][g][3] = 0.0f; }
            }
        }

        // ---- prefetch x(t+1) into regs (hidden under MMA) ----
        if (t + 1 < NT){
            #pragma unroll
            for (int j = 0; j < 10; j++) xv[j] = x[xoff[j] + (t+1)*HSTRIDE];
        }

        // ---- MMA per kf: x@Ux (gates 0-3) then h@V (gates 0-5) ----
        #pragma unroll
        for (int kf = 0; kf < 4; kf++){
            {   // x part
                u32 Xh[3][4], Xl[3][4];
                #pragma unroll
                for (int mi = 0; mi < 3; mi++){
                    ldsm_x4(Xh[mi][0],Xh[mi][1],Xh[mi][2],Xh[mi][3], rowAx[mi] + kf*32);
                    ldsm_x4(Xl[mi][0],Xl[mi][1],Xl[mi][2],Xl[mi][3], rowAx[mi] + 128 + kf*32);
                }
                u32 Uh[4][2], Ul[4][2];
                #pragma unroll
                for (int g = 0; g < 4; g++){
                    ldsm_x2(Uh[g][0], Uh[g][1], rowBU[g] + kf*32);
                    ldsm_x2(Ul[g][0], Ul[g][1], rowBU[g] + 128 + kf*32);
                }
                #pragma unroll
                for (int g = 0; g < 4; g++)
                    #pragma unroll
                    for (int mi = 0; mi < 3; mi++){
                        mma16816(acc[mi][g], Xh[mi], Uh[g]);
                        mma16816(acc[mi][g], Xh[mi], Ul[g]);
                        mma16816(acc[mi][g], Xl[mi], Uh[g]);
                    }
            }
            {   // h part
                u32 Hh[3][4], Hl[3][4];
                #pragma unroll
                for (int mi = 0; mi < 3; mi++){
                    ldsm_x4(Hh[mi][0],Hh[mi][1],Hh[mi][2],Hh[mi][3], rowAh[mi] + kf*32);
                    ldsm_x4(Hl[mi][0],Hl[mi][1],Hl[mi][2],Hl[mi][3], rowAh[mi] + 128 + kf*32);
                }
                u32 Vh[6][2], Vl[6][2];
                #pragma unroll
                for (int g = 0; g < 6; g++){
                    ldsm_x2(Vh[g][0], Vh[g][1], rowBV[g] + kf*32);
                    ldsm_x2(Vl[g][0], Vl[g][1], rowBV[g] + 128 + kf*32);
                }
                #pragma unroll
                for (int g = 0; g < 6; g++)
                    #pragma unroll
                    for (int mi = 0; mi < 3; mi++){
                        mma16816(acc[mi][g], Hh[mi], Vh[g]);
                        mma16816(acc[mi][g], Hh[mi], Vl[g]);
                        mma16816(acc[mi][g], Hl[mi], Vh[g]);
                    }
            }
        }
        __syncthreads();   // all reads of h(t-1), x_a(t) done

        // ---- stage oap(t+1) (overlaps EW; self-owned slots, read next top) ----
        if (t + 1 < NT){
            #pragma unroll
            for (int rg = 0; rg < 5; rg++){
                const float* p = g_G + ((size_t)(t+1)*NROWS + rhoA[rg])*128 + hcol;
                CP_ASYNC8(sb + SB_OS + (u32)((rg*2 + 0)*256 + tid)*8, p);
                CP_ASYNC8(sb + SB_OS + (u32)((rg*2 + 1)*256 + tid)*8, p + 64);
            }
            CP_COMMIT();
        }

        // ---- convert x(t+1) into x_a ----
        if (t + 1 < NT){
            #pragma unroll
            for (int j = 0; j < 10; j++){
                int i = tid + j*P2_THREADS;
                int row = i >> 6, k = i & 63;
                __nv_bfloat16 hb = __float2bfloat16(xv[j]);
                *(u16*)(smem + SB_X + row*HPITCH + 2*k) = __bfloat16_as_ushort(hb);
                *(u16*)(smem + SB_X + row*HPITCH + 128 + 2*k) =
                    __bfloat16_as_ushort(__float2bfloat16(xv[j] - __bfloat162float(hb)));
            }
        }

        // ---- EW in registers: 5 element-pairs ----
        #pragma unroll
        for (int rg = 0; rg < 5; rg++){
            int mi = rg >> 1, hm = rg & 1;
            float gf0 = acc[mi][0][2*hm], gf1 = acc[mi][0][2*hm+1];
            float gi0 = acc[mi][1][2*hm], gi1 = acc[mi][1][2*hm+1];
            float go0 = acc[mi][2][2*hm], go1 = acc[mi][2][2*hm+1];
            float gu0 = acc[mi][3][2*hm], gu1 = acc[mi][3][2*hm+1];
            float gG0 = acc[mi][4][2*hm], gG1 = acc[mi][4][2*hm+1];
            float gV0 = acc[mi][5][2*hm], gV1 = acc[mi][5][2*hm+1];

            float hn0, hn1;
            {
                float ef = __expf(-gf0);
                float eg = __expf(-gG0);
                float fgf = __fdividef(1.0f, 1.0f + ef + eg + ef*eg);
                float ei = __expf(-gi0);
                float eu = __expf(-gu0);
                float ev = __expf(-gV0);
                float iuu = __fdividef(1.0f, (1.0f+ei)*(1.0f+eu)*(1.0f+ev));
                float c = fgf*cst0[rg] + iuu;
                cst0[rg] = c;
                float ot = __fdividef(1.0f, 1.0f + __expf(-go0));
                float th = 1.0f - __fdividef(2.0f, 1.0f + __expf(2.0f*c));
                hn0 = ot * th;
            }
            {
                float ef = __expf(-gf1);
                float eg = __expf(-gG1);
                float fgf = __fdividef(1.0f, 1.0f + ef + eg + ef*eg);
                float ei = __expf(-gi1);
                float eu = __expf(-gu1);
                float ev = __expf(-gV1);
                float iuu = __fdividef(1.0f, (1.0f+ei)*(1.0f+eu)*(1.0f+ev));
                float c = fgf*cst1[rg] + iuu;
                cst1[rg] = c;
                float ot = __fdividef(1.0f, 1.0f + __expf(-go1));
                float th = 1.0f - __fdividef(2.0f, 1.0f + __expf(2.0f*c));
                hn1 = ot * th;
            }

            u32 hhi = bfpack(hn0, hn1);
            float r0 = hn0 - __uint_as_float(hhi << 16);
            float r1 = hn1 - __uint_as_float(hhi & 0xFFFF0000u);
            u32 hlo = bfpack(r0, r1);
            *(u32*)(smem + SB_H + rrow[rg]*HPITCH + 4*hpi)       = hhi;
            *(u32*)(smem + SB_H + rrow[rg]*HPITCH + 128 + 4*hpi) = hlo;

            float2 hv = make_float2(hn0, hn1);
            *(float2*)&hidden[gb[rg] + t*HSTRIDE] = hv;
            if (t == NT-1){
                *(float2*)&htp[fb[rg]] = hv;
                *(float2*)&ctp[fb[rg]] = make_float2(cst0[rg], cst1[rg]);
            }
        }
        __syncthreads();   // h(t) + x_a(t+1) published
    }
}

extern "C" void kernel_launch(void* const* d_in, const int* in_sizes, int n_in,
                              void* d_out, int out_size)
{
    const float* x   = (const float*)d_in[0];
    const float* o_s = (const float*)d_in[1];
    const float* Ux  = (const float*)d_in[2];
    const float* Vx  = (const float*)d_in[3];
    const float* bx  = (const float*)d_in[4];
    const float* Ug  = (const float*)d_in[5];
    const float* Vg  = (const float*)d_in[6];
    const float* bg  = (const float*)d_in[7];

    float* out    = (float*)d_out;
    float* hidden = out;                               // [B,T,N,H]
    float* htp    = out + (size_t)BTN * NH;            // [B,N,H]
    float* ctp    = htp + (size_t)NROWS * NH;          // [B,N,H]

    cudaFuncSetAttribute(glstm_pre_g,     cudaFuncAttributeMaxDynamicSharedMemorySize, Q_SMEM);
    cudaFuncSetAttribute(glstm_rec_fused, cudaFuncAttributeMaxDynamicSharedMemorySize, P2_SMEM);

    glstm_pre_g<<<Q_GRID, Q_THREADS, Q_SMEM>>>(o_s, Ug, bg);
    glstm_rec_fused<<<P2_BLOCKS, P2_THREADS, P2_SMEM>>>(x, Ux, bx, Vx, Vg,
                                                        hidden, htp, ctp);
}